// round 2
// baseline (speedup 1.0000x reference)
#include <cuda_runtime.h>
#include <cuda_bf16.h>
#include <cstdint>

// Problem constants
#define B_   2
#define S_   2048
#define H_   16
#define DH_  128
#define DM_  2048      // d_model
#define QKV_ (3*DM_)   // 6144
#define MROWS (B_*S_)  // 4096

// ---------------- scratch (no allocs allowed) ----------------
__device__ float g_qkv [(size_t)MROWS * QKV_];   // [4096, 6144]
__device__ float g_attn[(size_t)MROWS * DM_];    // [4096, 2048]

// ---------------- SGEMM 128x128x8, 256 thr, 8x8 per thread ----------------
#define BM 128
#define BN 128
#define BK 8
#define TM 8
#define TN 8

__global__ __launch_bounds__(256, 2)
void sgemm_bias(const float* __restrict__ A, const float* __restrict__ Bm,
                const float* __restrict__ bias, float* __restrict__ C,
                int M, int N, int K)
{
    __shared__ float As[BK][BM];   // A stored transposed
    __shared__ float Bs[BK][BN];

    const int bx = blockIdx.x;     // N tile
    const int by = blockIdx.y;     // M tile
    const int tid = threadIdx.x;
    const int tx = tid % 16;
    const int ty = tid / 16;

    const float* Ab = A + (size_t)by * BM * K;
    const float* Bb = Bm + (size_t)bx * BN;

    float acc[TM][TN];
#pragma unroll
    for (int i = 0; i < TM; i++)
#pragma unroll
        for (int j = 0; j < TN; j++) acc[i][j] = 0.f;

    const int arow = tid >> 1;          // 0..127
    const int acol = (tid & 1) * 4;     // 0 or 4
    const int brow = tid >> 5;          // 0..7
    const int bcol = (tid & 31) * 4;

    for (int k0 = 0; k0 < K; k0 += BK) {
        float4 a4 = *reinterpret_cast<const float4*>(Ab + (size_t)arow * K + k0 + acol);
        As[acol + 0][arow] = a4.x;
        As[acol + 1][arow] = a4.y;
        As[acol + 2][arow] = a4.z;
        As[acol + 3][arow] = a4.w;
        float4 b4 = *reinterpret_cast<const float4*>(Bb + (size_t)(k0 + brow) * N + bcol);
        *reinterpret_cast<float4*>(&Bs[brow][bcol]) = b4;
        __syncthreads();

#pragma unroll
        for (int k = 0; k < BK; k++) {
            float ar[TM], br[TN];
#pragma unroll
            for (int i = 0; i < TM; i++) ar[i] = As[k][ty * TM + i];
#pragma unroll
            for (int j = 0; j < TN; j++) br[j] = Bs[k][tx * TN + j];
#pragma unroll
            for (int i = 0; i < TM; i++)
#pragma unroll
                for (int j = 0; j < TN; j++)
                    acc[i][j] += ar[i] * br[j];
        }
        __syncthreads();
    }

#pragma unroll
    for (int i = 0; i < TM; i++) {
        const size_t row = (size_t)by * BM + ty * TM + i;
#pragma unroll
        for (int j = 0; j < TN; j += 4) {
            const int col = bx * BN + tx * TN + j;
            float4 o;
            o.x = acc[i][j + 0] + bias[col + 0];
            o.y = acc[i][j + 1] + bias[col + 1];
            o.z = acc[i][j + 2] + bias[col + 2];
            o.w = acc[i][j + 3] + bias[col + 3];
            *reinterpret_cast<float4*>(C + row * N + col) = o;
        }
    }
}

// ---------------- flash attention, fp32, causal ----------------
// grid: x = q-tile (S/64 = 32), y = b*H + h (32). 256 threads.
// thread (r = tid%64, chunk = tid/64): owns o[r, chunk*32 .. +31]
#define FBM 64
#define QPAD 129
#define PPAD 65

__global__ __launch_bounds__(256, 1)
void flash_attn(const float* __restrict__ qkv, float* __restrict__ out)
{
    extern __shared__ float sm[];
    float* Qs   = sm;                    // 64 * 129
    float* Ks   = Qs + FBM * QPAD;       // 64 * 128
    float* Vs   = Ks + FBM * DH_;        // 64 * 128
    float* Ps   = Vs + FBM * DH_;        // 64 * 65
    float* mrow = Ps + FBM * PPAD;       // 64
    float* lrow = mrow + FBM;            // 64
    float* arow = lrow + FBM;            // 64

    const int bh = blockIdx.y;
    const int b  = bh / H_;
    const int h  = bh % H_;
    const int qt = blockIdx.x;
    const int q0 = qt * FBM;
    const int tid = threadIdx.x;
    const int r = tid % 64;
    const int chunk = tid / 64;
    const float scale = 0.08838834764831845f;   // 1/sqrt(128)

    const float* base = qkv + (size_t)b * S_ * QKV_ + (size_t)h * DH_;

    // load Q tile (scalar, into padded smem -> conflict-free later)
    for (int i = tid; i < FBM * DH_; i += 256) {
        int rr = i >> 7, dd = i & 127;
        Qs[rr * QPAD + dd] = base[(size_t)(q0 + rr) * QKV_ + dd];
    }
    if (tid < 64) { mrow[tid] = -1e30f; lrow[tid] = 0.f; }

    float o[32];
#pragma unroll
    for (int i = 0; i < 32; i++) o[i] = 0.f;
    __syncthreads();

    for (int jt = 0; jt <= qt; jt++) {
        const int k0 = jt * FBM;
        // load K, V tiles (vectorized)
        for (int i = tid; i < FBM * 32; i += 256) {
            int rr = i >> 5, d4 = (i & 31) * 4;
            const float* rowp = base + (size_t)(k0 + rr) * QKV_;
            *reinterpret_cast<float4*>(&Ks[rr * DH_ + d4]) =
                *reinterpret_cast<const float4*>(rowp + DM_ + d4);
            *reinterpret_cast<float4*>(&Vs[rr * DH_ + d4]) =
                *reinterpret_cast<const float4*>(rowp + 2 * DM_ + d4);
        }
        __syncthreads();

        // scores: this thread computes cols [chunk*16, chunk*16+16) for row r
        float s[16];
#pragma unroll
        for (int c = 0; c < 16; c++) s[c] = 0.f;
#pragma unroll 4
        for (int d = 0; d < DH_; d++) {
            float qd = Qs[r * QPAD + d];
#pragma unroll
            for (int c = 0; c < 16; c++)
                s[c] += qd * Ks[(chunk * 16 + c) * DH_ + d];   // broadcast read
        }
        const bool diag = (jt == qt);
#pragma unroll
        for (int c = 0; c < 16; c++) {
            int cc = chunk * 16 + c;
            float val = s[c] * scale;
            if (diag && (k0 + cc) > (q0 + r)) val = -1e30f;
            Ps[r * PPAD + cc] = val;
        }
        __syncthreads();

        // online softmax per row (64 worker threads)
        if (tid < 64) {
            const int rr = tid;
            float mold = mrow[rr];
            float mx = mold;
#pragma unroll 8
            for (int c = 0; c < 64; c++) mx = fmaxf(mx, Ps[rr * PPAD + c]);
            float alpha = __expf(mold - mx);
            float sum = 0.f;
#pragma unroll 8
            for (int c = 0; c < 64; c++) {
                float p = __expf(Ps[rr * PPAD + c] - mx);
                Ps[rr * PPAD + c] = p;
                sum += p;
            }
            mrow[rr] = mx;
            lrow[rr] = lrow[rr] * alpha + sum;
            arow[rr] = alpha;
        }
        __syncthreads();

        // O update
        const float alpha = arow[r];
#pragma unroll
        for (int d = 0; d < 32; d++) o[d] *= alpha;
#pragma unroll 2
        for (int c = 0; c < 64; c++) {
            float p = Ps[r * PPAD + c];               // (r+c)%32 -> conflict-free
            const float* vp = &Vs[c * DH_ + chunk * 32];  // broadcast
#pragma unroll
            for (int d = 0; d < 32; d++)
                o[d] += p * vp[d];
        }
        __syncthreads();
    }

    const float inv = 1.f / lrow[r];
    float* op = out + (size_t)(b * S_ + q0 + r) * DM_ + h * DH_ + chunk * 32;
#pragma unroll
    for (int d = 0; d < 32; d++) op[d] = o[d] * inv;
}

// ---------------- launch ----------------
extern "C" void kernel_launch(void* const* d_in, const int* in_sizes, int n_in,
                              void* d_out, int out_size)
{
    const float* x     = (const float*)d_in[0];   // [2,2048,2048]
    const float* W_qkv = (const float*)d_in[1];   // [2048,6144]
    const float* b_qkv = (const float*)d_in[2];   // [6144]
    const float* W_out = (const float*)d_in[3];   // [2048,2048]
    const float* b_out = (const float*)d_in[4];   // [2048]
    float* out = (float*)d_out;

    float* qkv;  cudaGetSymbolAddress((void**)&qkv,  g_qkv);
    float* attn; cudaGetSymbolAddress((void**)&attn, g_attn);

    // 1) QKV projection: [4096,2048] @ [2048,6144] + bias
    {
        dim3 grid(QKV_ / BN, MROWS / BM);
        sgemm_bias<<<grid, 256>>>(x, W_qkv, b_qkv, qkv, MROWS, QKV_, DM_);
    }

    // 2) causal multi-head attention
    {
        int smem = (FBM * QPAD + 2 * FBM * DH_ + FBM * PPAD + 3 * FBM) * sizeof(float);
        cudaFuncSetAttribute(flash_attn, cudaFuncAttributeMaxDynamicSharedMemorySize, smem);
        dim3 grid(S_ / FBM, B_ * H_);
        flash_attn<<<grid, 256, smem>>>(qkv, attn);
    }

    // 3) output projection: [4096,2048] @ [2048,2048] + bias
    {
        dim3 grid(DM_ / BN, MROWS / BM);
        sgemm_bias<<<grid, 256>>>(attn, W_out, b_out, out, MROWS, DM_, DM_);
    }
}

// round 4
// speedup vs baseline: 1.8936x; 1.8936x over previous
#include <cuda_runtime.h>
#include <cuda_bf16.h>
#include <cstdint>

// Problem constants
#define B_   2
#define S_   2048
#define H_   16
#define DH_  128
#define DM_  2048
#define QKV_ (3*DM_)   // 6144
#define MROWS (B_*S_)  // 4096

typedef __nv_bfloat16 bf16;

// ---------------- scratch (no allocs allowed) ----------------
__device__ float g_qkv [(size_t)MROWS * QKV_];          // fp32 QKV for attention
__device__ bf16  g_xhi [(size_t)MROWS * DM_];
__device__ bf16  g_xlo [(size_t)MROWS * DM_];
__device__ bf16  g_wqh [(size_t)QKV_ * DM_];            // W_qkv^T [6144,2048] K-major
__device__ bf16  g_wql [(size_t)QKV_ * DM_];
__device__ bf16  g_woh [(size_t)DM_ * DM_];             // W_out^T [2048,2048] K-major
__device__ bf16  g_wol [(size_t)DM_ * DM_];
__device__ bf16  g_ahi [(size_t)MROWS * DM_];           // attention out hi/lo
__device__ bf16  g_alo [(size_t)MROWS * DM_];

// =================== helpers ===================
__device__ __forceinline__ uint32_t smem_u32(const void* p) {
    uint32_t a;
    asm("{ .reg .u64 t; cvta.to.shared.u64 t, %1; cvt.u32.u64 %0, t; }" : "=r"(a) : "l"(p));
    return a;
}
#define SW128(o) ((o) ^ (((o) >> 3) & 0x70))

#define CP_ASYNC16(sa, gp) \
    asm volatile("cp.async.cg.shared.global [%0], [%1], 16;" :: "r"(sa), "l"(gp) : "memory")
#define CP_COMMIT()  asm volatile("cp.async.commit_group;" ::: "memory")
#define CP_WAIT1()   asm volatile("cp.async.wait_group 1;" ::: "memory")
#define CP_WAIT0()   asm volatile("cp.async.wait_group 0;" ::: "memory")

#define LDMATRIX_X4(r0, r1, r2, r3, addr) \
    asm volatile("ldmatrix.sync.aligned.m8n8.x4.shared.b16 {%0,%1,%2,%3}, [%4];" \
        : "=r"(r0), "=r"(r1), "=r"(r2), "=r"(r3) : "r"(addr))

__device__ __forceinline__ void mma16816(float* d, const uint32_t* a,
                                         const uint32_t b0, const uint32_t b1) {
    asm volatile(
        "mma.sync.aligned.m16n8k16.row.col.f32.bf16.bf16.f32 "
        "{%0,%1,%2,%3}, {%4,%5,%6,%7}, {%8,%9}, {%0,%1,%2,%3};"
        : "+f"(d[0]), "+f"(d[1]), "+f"(d[2]), "+f"(d[3])
        : "r"(a[0]), "r"(a[1]), "r"(a[2]), "r"(a[3]), "r"(b0), "r"(b1));
}

// =================== prep kernels ===================
__global__ void split_x_kernel(const float* __restrict__ in, bf16* __restrict__ oh,
                               bf16* __restrict__ ol, size_t n4)
{
    size_t i = (size_t)blockIdx.x * blockDim.x + threadIdx.x;
    if (i >= n4) return;
    float4 v = reinterpret_cast<const float4*>(in)[i];
    bf16 h0 = __float2bfloat16(v.x), h1 = __float2bfloat16(v.y);
    bf16 h2 = __float2bfloat16(v.z), h3 = __float2bfloat16(v.w);
    bf16 l0 = __float2bfloat16(v.x - __bfloat162float(h0));
    bf16 l1 = __float2bfloat16(v.y - __bfloat162float(h1));
    bf16 l2 = __float2bfloat16(v.z - __bfloat162float(h2));
    bf16 l3 = __float2bfloat16(v.w - __bfloat162float(h3));
    reinterpret_cast<__nv_bfloat162*>(oh)[2*i]   = __nv_bfloat162(h0, h1);
    reinterpret_cast<__nv_bfloat162*>(oh)[2*i+1] = __nv_bfloat162(h2, h3);
    reinterpret_cast<__nv_bfloat162*>(ol)[2*i]   = __nv_bfloat162(l0, l1);
    reinterpret_cast<__nv_bfloat162*>(ol)[2*i+1] = __nv_bfloat162(l2, l3);
}

// in [K,N] f32 -> out [N,K] bf16 hi/lo
__global__ void transpose_split_kernel(const float* __restrict__ in,
                                       bf16* __restrict__ oh, bf16* __restrict__ ol,
                                       int K, int N)
{
    __shared__ float t[32][33];
    int bx = blockIdx.x, by = blockIdx.y;
    int tx = threadIdx.x, ty = threadIdx.y;
#pragma unroll
    for (int i = 0; i < 4; i++)
        t[ty + 8*i][tx] = in[(size_t)(by*32 + ty + 8*i) * N + bx*32 + tx];
    __syncthreads();
#pragma unroll
    for (int i = 0; i < 4; i++) {
        float v = t[tx][ty + 8*i];
        bf16 h = __float2bfloat16(v);
        bf16 l = __float2bfloat16(v - __bfloat162float(h));
        size_t o = (size_t)(bx*32 + ty + 8*i) * K + by*32 + tx;
        oh[o] = h; ol[o] = l;
    }
}

// =================== mma.sync split-bf16 GEMM ===================
// C[M,N] = (Ah+Al)[M,K] @ (Bh+Bl)^T + bias.  B stored [N,K] K-major.
// CTA tile 128x128, BK=64, 8 warps (4x2), warp tile 32x64.
#define GBM 128
#define GBN 128
#define GKC 64
#define STAGE_BYTES 65536       // 4 tiles (Ah,Al,Bh,Bl) x 16KB

__global__ __launch_bounds__(256, 1)
void gemm_mma_split(const bf16* __restrict__ Ah, const bf16* __restrict__ Al,
                    const bf16* __restrict__ Bh, const bf16* __restrict__ Bl,
                    const float* __restrict__ bias, float* __restrict__ C,
                    int Ndim, int Kdim)
{
    extern __shared__ char smem[];
    const uint32_t sbase = smem_u32(smem);
    const int tid  = threadIdx.x;
    const int wid  = tid >> 5;
    const int lane = tid & 31;
    const int wm = wid & 3;              // 0..3 -> m offset wm*32
    const int wn = wid >> 2;             // 0..1 -> n offset wn*64
    const int m0 = blockIdx.y * GBM;
    const int n0 = blockIdx.x * GBN;

    const bf16* pAh = Ah + (size_t)m0 * Kdim;
    const bf16* pAl = Al + (size_t)m0 * Kdim;
    const bf16* pBh = Bh + (size_t)n0 * Kdim;
    const bf16* pBl = Bl + (size_t)n0 * Kdim;

    float acc[2][8][4];
#pragma unroll
    for (int i = 0; i < 2; i++)
#pragma unroll
        for (int j = 0; j < 8; j++)
#pragma unroll
            for (int k = 0; k < 4; k++) acc[i][j][k] = 0.f;

    const int NKC = Kdim / GKC;
    const int lrow = tid >> 3;           // 0..31 within strided copy
    const int lc16 = tid & 7;            // 16B chunk within 128B row

    // ---- async copy of one chunk into stage buffer ----
    auto load_chunk = [&](int kc, int buf) {
        const uint32_t bb = sbase + buf * STAGE_BYTES;
        const int k0 = kc * GKC;
#pragma unroll
        for (int rr = 0; rr < 4; rr++) {
            int row = lrow + rr * 32;
            uint32_t so = SW128((uint32_t)(row * 128 + lc16 * 16));
            size_t go = (size_t)row * Kdim + k0 + lc16 * 8;
            CP_ASYNC16(bb +         so, pAh + go);
            CP_ASYNC16(bb + 16384 + so, pAl + go);
            CP_ASYNC16(bb + 32768 + so, pBh + go);
            CP_ASYNC16(bb + 49152 + so, pBl + go);
        }
    };

    // ldmatrix lane address offsets (within a 16KB tile), per k-step added later
    //   A (x4): rows base+(lane&15), kbyte (lane>>4)*16
    //   B (x4): rows base+(lane&7)+((lane&16)?8:0), kbyte (lane&8)?16:0
    const int a_row = (lane & 15);
    const int a_kb  = (lane >> 4) * 16;
    const int b_row = (lane & 7) + ((lane & 16) ? 8 : 0);
    const int b_kb  = (lane & 8) ? 16 : 0;

    load_chunk(0, 0);
    CP_COMMIT();

    for (int kc = 0; kc < NKC; kc++) {
        if (kc + 1 < NKC) load_chunk(kc + 1, (kc + 1) & 1);
        CP_COMMIT();
        CP_WAIT1();
        __syncthreads();

        const uint32_t bb = sbase + (kc & 1) * STAGE_BYTES;
        const uint32_t sAh = bb, sAl = bb + 16384, sBh = bb + 32768, sBl = bb + 49152;

#pragma unroll
        for (int ks = 0; ks < 4; ks++) {
            const int kb = ks * 32;     // byte offset of this k16 step
            uint32_t ah[2][4], al[2][4], bh[4][4], bl[4][4];
#pragma unroll
            for (int mi = 0; mi < 2; mi++) {
                int row = wm * 32 + mi * 16 + a_row;
                uint32_t so = SW128((uint32_t)(row * 128 + kb + a_kb));
                LDMATRIX_X4(ah[mi][0], ah[mi][1], ah[mi][2], ah[mi][3], sAh + so);
                LDMATRIX_X4(al[mi][0], al[mi][1], al[mi][2], al[mi][3], sAl + so);
            }
#pragma unroll
            for (int pi = 0; pi < 4; pi++) {
                int row = wn * 64 + pi * 16 + b_row;
                uint32_t so = SW128((uint32_t)(row * 128 + kb + b_kb));
                LDMATRIX_X4(bh[pi][0], bh[pi][1], bh[pi][2], bh[pi][3], sBh + so);
                LDMATRIX_X4(bl[pi][0], bl[pi][1], bl[pi][2], bl[pi][3], sBl + so);
            }
#pragma unroll
            for (int mi = 0; mi < 2; mi++)
#pragma unroll
                for (int ni = 0; ni < 8; ni++) {
                    const int pi = ni >> 1, sel = (ni & 1) * 2;
                    mma16816(acc[mi][ni], ah[mi], bh[pi][sel], bh[pi][sel + 1]);
                    mma16816(acc[mi][ni], ah[mi], bl[pi][sel], bl[pi][sel + 1]);
                    mma16816(acc[mi][ni], al[mi], bh[pi][sel], bh[pi][sel + 1]);
                }
        }
        __syncthreads();
    }
    CP_WAIT0();

    // ---- epilogue: bias + store (float2 per reg pair) ----
#pragma unroll
    for (int mi = 0; mi < 2; mi++) {
        const int r_lo = m0 + wm * 32 + mi * 16 + (lane >> 2);
        const int r_hi = r_lo + 8;
#pragma unroll
        for (int ni = 0; ni < 8; ni++) {
            const int ncol = n0 + wn * 64 + ni * 8 + (lane & 3) * 2;
            const float2 b2 = *reinterpret_cast<const float2*>(bias + ncol);
            float2 v0, v1;
            v0.x = acc[mi][ni][0] + b2.x; v0.y = acc[mi][ni][1] + b2.y;
            v1.x = acc[mi][ni][2] + b2.x; v1.y = acc[mi][ni][3] + b2.y;
            *reinterpret_cast<float2*>(C + (size_t)r_lo * Ndim + ncol) = v0;
            *reinterpret_cast<float2*>(C + (size_t)r_hi * Ndim + ncol) = v1;
        }
    }
}

// =================== flash attention (fp32, causal) ===================
#define FBM 64
#define QPAD 129
#define PPAD 65

__global__ __launch_bounds__(256, 1)
void flash_attn(const float* __restrict__ qkv, bf16* __restrict__ outh,
                bf16* __restrict__ outl)
{
    extern __shared__ float sm[];
    float* Qs   = sm;
    float* Ks   = Qs + FBM * QPAD;
    float* Vs   = Ks + FBM * DH_;
    float* Ps   = Vs + FBM * DH_;
    float* mrow = Ps + FBM * PPAD;
    float* lrow = mrow + FBM;
    float* arow = lrow + FBM;

    const int bh = blockIdx.y;
    const int b  = bh / H_;
    const int h  = bh % H_;
    const int qt = blockIdx.x;
    const int q0 = qt * FBM;
    const int tid = threadIdx.x;
    const int r = tid % 64;
    const int chunk = tid / 64;
    const float scale = 0.08838834764831845f;

    const float* base = qkv + (size_t)b * S_ * QKV_ + (size_t)h * DH_;

    for (int i = tid; i < FBM * DH_; i += 256) {
        int rr = i >> 7, dd = i & 127;
        Qs[rr * QPAD + dd] = base[(size_t)(q0 + rr) * QKV_ + dd];
    }
    if (tid < 64) { mrow[tid] = -1e30f; lrow[tid] = 0.f; }

    float o[32];
#pragma unroll
    for (int i = 0; i < 32; i++) o[i] = 0.f;
    __syncthreads();

    for (int jt = 0; jt <= qt; jt++) {
        const int k0 = jt * FBM;
        for (int i = tid; i < FBM * 32; i += 256) {
            int rr = i >> 5, d4 = (i & 31) * 4;
            const float* rowp = base + (size_t)(k0 + rr) * QKV_;
            *reinterpret_cast<float4*>(&Ks[rr * DH_ + d4]) =
                *reinterpret_cast<const float4*>(rowp + DM_ + d4);
            *reinterpret_cast<float4*>(&Vs[rr * DH_ + d4]) =
                *reinterpret_cast<const float4*>(rowp + 2 * DM_ + d4);
        }
        __syncthreads();

        float s[16];
#pragma unroll
        for (int c = 0; c < 16; c++) s[c] = 0.f;
#pragma unroll 4
        for (int d = 0; d < DH_; d++) {
            float qd = Qs[r * QPAD + d];
#pragma unroll
            for (int c = 0; c < 16; c++)
                s[c] += qd * Ks[(chunk * 16 + c) * DH_ + d];
        }
        const bool diag = (jt == qt);
#pragma unroll
        for (int c = 0; c < 16; c++) {
            int cc = chunk * 16 + c;
            float val = s[c] * scale;
            if (diag && (k0 + cc) > (q0 + r)) val = -1e30f;
            Ps[r * PPAD + cc] = val;
        }
        __syncthreads();

        if (tid < 64) {
            const int rr = tid;
            float mold = mrow[rr];
            float mx = mold;
#pragma unroll 8
            for (int c = 0; c < 64; c++) mx = fmaxf(mx, Ps[rr * PPAD + c]);
            float alpha = __expf(mold - mx);
            float sum = 0.f;
#pragma unroll 8
            for (int c = 0; c < 64; c++) {
                float p = __expf(Ps[rr * PPAD + c] - mx);
                Ps[rr * PPAD + c] = p;
                sum += p;
            }
            mrow[rr] = mx;
            lrow[rr] = lrow[rr] * alpha + sum;
            arow[rr] = alpha;
        }
        __syncthreads();

        const float alpha = arow[r];
#pragma unroll
        for (int d = 0; d < 32; d++) o[d] *= alpha;
#pragma unroll 2
        for (int c = 0; c < 64; c++) {
            float p = Ps[r * PPAD + c];
            const float* vp = &Vs[c * DH_ + chunk * 32];
#pragma unroll
            for (int d = 0; d < 32; d++)
                o[d] += p * vp[d];
        }
        __syncthreads();
    }

    const float inv = 1.f / lrow[r];
    size_t off = (size_t)(b * S_ + q0 + r) * DM_ + h * DH_ + chunk * 32;
#pragma unroll
    for (int d = 0; d < 32; d++) {
        float v = o[d] * inv;
        bf16 hv = __float2bfloat16(v);
        bf16 lv = __float2bfloat16(v - __bfloat162float(hv));
        outh[off + d] = hv;
        outl[off + d] = lv;
    }
}

// =================== launch ===================
extern "C" void kernel_launch(void* const* d_in, const int* in_sizes, int n_in,
                              void* d_out, int out_size)
{
    const float* x     = (const float*)d_in[0];
    const float* W_qkv = (const float*)d_in[1];
    const float* b_qkv = (const float*)d_in[2];
    const float* W_out = (const float*)d_in[3];
    const float* b_out = (const float*)d_in[4];
    float* out = (float*)d_out;

    float* qkv; cudaGetSymbolAddress((void**)&qkv, g_qkv);
    bf16 *xhi, *xlo, *wqh, *wql, *woh, *wol, *ahi, *alo;
    cudaGetSymbolAddress((void**)&xhi, g_xhi);
    cudaGetSymbolAddress((void**)&xlo, g_xlo);
    cudaGetSymbolAddress((void**)&wqh, g_wqh);
    cudaGetSymbolAddress((void**)&wql, g_wql);
    cudaGetSymbolAddress((void**)&woh, g_woh);
    cudaGetSymbolAddress((void**)&wol, g_wol);
    cudaGetSymbolAddress((void**)&ahi, g_ahi);
    cudaGetSymbolAddress((void**)&alo, g_alo);

    // prep: split x, transpose+split weights
    {
        size_t n4 = (size_t)MROWS * DM_ / 4;
        split_x_kernel<<<(unsigned)((n4 + 255) / 256), 256>>>(x, xhi, xlo, n4);
        dim3 blk(32, 8);
        transpose_split_kernel<<<dim3(QKV_ / 32, DM_ / 32), blk>>>(W_qkv, wqh, wql, DM_, QKV_);
        transpose_split_kernel<<<dim3(DM_ / 32, DM_ / 32), blk>>>(W_out, woh, wol, DM_, DM_);
    }

    const int gemm_smem = 2 * STAGE_BYTES;   // 128KB
    cudaFuncSetAttribute(gemm_mma_split, cudaFuncAttributeMaxDynamicSharedMemorySize, gemm_smem);

    // 1) QKV projection: [4096,2048] @ [2048,6144] + bias
    gemm_mma_split<<<dim3(QKV_ / GBN, MROWS / GBM), 256, gemm_smem>>>(
        xhi, xlo, wqh, wql, b_qkv, qkv, QKV_, DM_);

    // 2) causal multi-head attention (writes hi/lo bf16)
    {
        int smem = (FBM * QPAD + 2 * FBM * DH_ + FBM * PPAD + 3 * FBM) * sizeof(float);
        cudaFuncSetAttribute(flash_attn, cudaFuncAttributeMaxDynamicSharedMemorySize, smem);
        flash_attn<<<dim3(S_ / FBM, B_ * H_), 256, smem>>>(qkv, ahi, alo);
    }

    // 3) output projection: [4096,2048] @ [2048,2048] + bias
    gemm_mma_split<<<dim3(DM_ / GBN, MROWS / GBM), 256, gemm_smem>>>(
        ahi, alo, woh, wol, b_out, out, DM_, DM_);
}

// round 7
// speedup vs baseline: 3.6853x; 1.9462x over previous
#include <cuda_runtime.h>
#include <cuda_bf16.h>
#include <cstdint>

// Problem constants
#define B_   2
#define S_   2048
#define H_   16
#define DH_  128
#define DM_  2048
#define QKV_ (3*DM_)   // 6144
#define MROWS (B_*S_)  // 4096

typedef __nv_bfloat16 bf16;

// ---------------- scratch (no allocs allowed) ----------------
__device__ bf16  g_qkvh[(size_t)MROWS * QKV_];          // QKV hi [4096,6144]
__device__ bf16  g_qkvl[(size_t)MROWS * QKV_];          // QKV lo
__device__ bf16  g_xhi [(size_t)MROWS * DM_];
__device__ bf16  g_xlo [(size_t)MROWS * DM_];
__device__ bf16  g_wqh [(size_t)QKV_ * DM_];            // W_qkv^T [6144,2048] K-major
__device__ bf16  g_wql [(size_t)QKV_ * DM_];
__device__ bf16  g_woh [(size_t)DM_ * DM_];             // W_out^T [2048,2048] K-major
__device__ bf16  g_wol [(size_t)DM_ * DM_];
__device__ bf16  g_ahi [(size_t)MROWS * DM_];           // attention out hi/lo
__device__ bf16  g_alo [(size_t)MROWS * DM_];

// =================== helpers ===================
__device__ __forceinline__ uint32_t smem_u32(const void* p) {
    uint32_t a;
    asm("{ .reg .u64 t; cvta.to.shared.u64 t, %1; cvt.u32.u64 %0, t; }" : "=r"(a) : "l"(p));
    return a;
}
#define SW128(o) ((o) ^ (((o) >> 3) & 0x70))
// 256B-row swizzle: XOR the 32B-chunk index with (row & 7)
__device__ __forceinline__ uint32_t sw256(int row, int cb) {
    return (uint32_t)(row * 256 + ((((cb >> 5) ^ (row & 7)) << 5) | (cb & 31)));
}

#define CP_ASYNC16(sa, gp) \
    asm volatile("cp.async.cg.shared.global [%0], [%1], 16;" :: "r"(sa), "l"(gp) : "memory")
#define CP_COMMIT()  asm volatile("cp.async.commit_group;" ::: "memory")
#define CP_WAIT1()   asm volatile("cp.async.wait_group 1;" ::: "memory")
#define CP_WAIT0()   asm volatile("cp.async.wait_group 0;" ::: "memory")

#define LDMATRIX_X4(r0, r1, r2, r3, addr) \
    asm volatile("ldmatrix.sync.aligned.m8n8.x4.shared.b16 {%0,%1,%2,%3}, [%4];" \
        : "=r"(r0), "=r"(r1), "=r"(r2), "=r"(r3) : "r"(addr))
#define LDMATRIX_X4_T(r0, r1, r2, r3, addr) \
    asm volatile("ldmatrix.sync.aligned.m8n8.x4.trans.shared.b16 {%0,%1,%2,%3}, [%4];" \
        : "=r"(r0), "=r"(r1), "=r"(r2), "=r"(r3) : "r"(addr))

__device__ __forceinline__ void mma16816(float* d, const uint32_t* a,
                                         const uint32_t b0, const uint32_t b1) {
    asm volatile(
        "mma.sync.aligned.m16n8k16.row.col.f32.bf16.bf16.f32 "
        "{%0,%1,%2,%3}, {%4,%5,%6,%7}, {%8,%9}, {%0,%1,%2,%3};"
        : "+f"(d[0]), "+f"(d[1]), "+f"(d[2]), "+f"(d[3])
        : "r"(a[0]), "r"(a[1]), "r"(a[2]), "r"(a[3]), "r"(b0), "r"(b1));
}

__device__ __forceinline__ void split2(float x, float y, uint32_t& h, uint32_t& l) {
    bf16 hx = __float2bfloat16(x), hy = __float2bfloat16(y);
    __nv_bfloat162 hp(hx, hy);
    __nv_bfloat162 lp(__float2bfloat16(x - __bfloat162float(hx)),
                      __float2bfloat16(y - __bfloat162float(hy)));
    h = *reinterpret_cast<uint32_t*>(&hp);
    l = *reinterpret_cast<uint32_t*>(&lp);
}

// =================== prep kernels ===================
__global__ void split_x_kernel(const float* __restrict__ in, bf16* __restrict__ oh,
                               bf16* __restrict__ ol, size_t n4)
{
    size_t i = (size_t)blockIdx.x * blockDim.x + threadIdx.x;
    if (i >= n4) return;
    float4 v = reinterpret_cast<const float4*>(in)[i];
    bf16 h0 = __float2bfloat16(v.x), h1 = __float2bfloat16(v.y);
    bf16 h2 = __float2bfloat16(v.z), h3 = __float2bfloat16(v.w);
    bf16 l0 = __float2bfloat16(v.x - __bfloat162float(h0));
    bf16 l1 = __float2bfloat16(v.y - __bfloat162float(h1));
    bf16 l2 = __float2bfloat16(v.z - __bfloat162float(h2));
    bf16 l3 = __float2bfloat16(v.w - __bfloat162float(h3));
    reinterpret_cast<__nv_bfloat162*>(oh)[2*i]   = __nv_bfloat162(h0, h1);
    reinterpret_cast<__nv_bfloat162*>(oh)[2*i+1] = __nv_bfloat162(h2, h3);
    reinterpret_cast<__nv_bfloat162*>(ol)[2*i]   = __nv_bfloat162(l0, l1);
    reinterpret_cast<__nv_bfloat162*>(ol)[2*i+1] = __nv_bfloat162(l2, l3);
}

// in [K,N] f32 -> out [N,K] bf16 hi/lo
__global__ void transpose_split_kernel(const float* __restrict__ in,
                                       bf16* __restrict__ oh, bf16* __restrict__ ol,
                                       int K, int N)
{
    __shared__ float t[32][33];
    int bx = blockIdx.x, by = blockIdx.y;
    int tx = threadIdx.x, ty = threadIdx.y;
#pragma unroll
    for (int i = 0; i < 4; i++)
        t[ty + 8*i][tx] = in[(size_t)(by*32 + ty + 8*i) * N + bx*32 + tx];
    __syncthreads();
#pragma unroll
    for (int i = 0; i < 4; i++) {
        float v = t[tx][ty + 8*i];
        bf16 h = __float2bfloat16(v);
        bf16 l = __float2bfloat16(v - __bfloat162float(h));
        size_t o = (size_t)(bx*32 + ty + 8*i) * K + by*32 + tx;
        oh[o] = h; ol[o] = l;
    }
}

// =================== mma.sync split-bf16 GEMM ===================
// C = (Ah+Al)[M,K] @ (Bh+Bl)^T + bias.  B stored [N,K] K-major.
// CTA tile 128x128, BK=64, 8 warps (4x2), warp tile 32x64.
// If Chi != nullptr: write hi/lo bf16 split instead of fp32.
#define GBM 128
#define GBN 128
#define GKC 64
#define STAGE_BYTES 65536       // 4 tiles (Ah,Al,Bh,Bl) x 16KB

__global__ __launch_bounds__(256, 1)
void gemm_mma_split(const bf16* __restrict__ Ah, const bf16* __restrict__ Al,
                    const bf16* __restrict__ Bh, const bf16* __restrict__ Bl,
                    const float* __restrict__ bias, float* __restrict__ C,
                    bf16* __restrict__ Chi, bf16* __restrict__ Clo,
                    int Ndim, int Kdim)
{
    extern __shared__ char smem[];
    const uint32_t sbase = smem_u32(smem);
    const int tid  = threadIdx.x;
    const int wid  = tid >> 5;
    const int lane = tid & 31;
    const int wm = wid & 3;
    const int wn = wid >> 2;
    const int m0 = blockIdx.y * GBM;
    const int n0 = blockIdx.x * GBN;

    const bf16* pAh = Ah + (size_t)m0 * Kdim;
    const bf16* pAl = Al + (size_t)m0 * Kdim;
    const bf16* pBh = Bh + (size_t)n0 * Kdim;
    const bf16* pBl = Bl + (size_t)n0 * Kdim;

    float acc[2][8][4];
#pragma unroll
    for (int i = 0; i < 2; i++)
#pragma unroll
        for (int j = 0; j < 8; j++)
#pragma unroll
            for (int k = 0; k < 4; k++) acc[i][j][k] = 0.f;

    const int NKC = Kdim / GKC;
    const int lrow = tid >> 3;
    const int lc16 = tid & 7;

    auto load_chunk = [&](int kc, int buf) {
        const uint32_t bb = sbase + buf * STAGE_BYTES;
        const int k0 = kc * GKC;
#pragma unroll
        for (int rr = 0; rr < 4; rr++) {
            int row = lrow + rr * 32;
            uint32_t so = SW128((uint32_t)(row * 128 + lc16 * 16));
            size_t go = (size_t)row * Kdim + k0 + lc16 * 8;
            CP_ASYNC16(bb +         so, pAh + go);
            CP_ASYNC16(bb + 16384 + so, pAl + go);
            CP_ASYNC16(bb + 32768 + so, pBh + go);
            CP_ASYNC16(bb + 49152 + so, pBl + go);
        }
    };

    const int a_row = (lane & 15);
    const int a_kb  = (lane >> 4) * 16;
    const int b_row = (lane & 7) + ((lane & 16) ? 8 : 0);
    const int b_kb  = (lane & 8) ? 16 : 0;

    load_chunk(0, 0);
    CP_COMMIT();

    for (int kc = 0; kc < NKC; kc++) {
        if (kc + 1 < NKC) load_chunk(kc + 1, (kc + 1) & 1);
        CP_COMMIT();
        CP_WAIT1();
        __syncthreads();

        const uint32_t bb = sbase + (kc & 1) * STAGE_BYTES;
        const uint32_t sAh = bb, sAl = bb + 16384, sBh = bb + 32768, sBl = bb + 49152;

#pragma unroll
        for (int ks = 0; ks < 4; ks++) {
            const int kb = ks * 32;
            uint32_t ah[2][4], al[2][4], bh[4][4], bl[4][4];
#pragma unroll
            for (int mi = 0; mi < 2; mi++) {
                int row = wm * 32 + mi * 16 + a_row;
                uint32_t so = SW128((uint32_t)(row * 128 + kb + a_kb));
                LDMATRIX_X4(ah[mi][0], ah[mi][1], ah[mi][2], ah[mi][3], sAh + so);
                LDMATRIX_X4(al[mi][0], al[mi][1], al[mi][2], al[mi][3], sAl + so);
            }
#pragma unroll
            for (int pi = 0; pi < 4; pi++) {
                int row = wn * 64 + pi * 16 + b_row;
                uint32_t so = SW128((uint32_t)(row * 128 + kb + b_kb));
                LDMATRIX_X4(bh[pi][0], bh[pi][1], bh[pi][2], bh[pi][3], sBh + so);
                LDMATRIX_X4(bl[pi][0], bl[pi][1], bl[pi][2], bl[pi][3], sBl + so);
            }
#pragma unroll
            for (int mi = 0; mi < 2; mi++)
#pragma unroll
                for (int ni = 0; ni < 8; ni++) {
                    const int pi = ni >> 1, sel = (ni & 1) * 2;
                    mma16816(acc[mi][ni], ah[mi], bh[pi][sel], bh[pi][sel + 1]);
                    mma16816(acc[mi][ni], ah[mi], bl[pi][sel], bl[pi][sel + 1]);
                    mma16816(acc[mi][ni], al[mi], bh[pi][sel], bh[pi][sel + 1]);
                }
        }
        __syncthreads();
    }
    CP_WAIT0();

    // ---- epilogue: bias + store ----
#pragma unroll
    for (int mi = 0; mi < 2; mi++) {
        const int r_lo = m0 + wm * 32 + mi * 16 + (lane >> 2);
        const int r_hi = r_lo + 8;
#pragma unroll
        for (int ni = 0; ni < 8; ni++) {
            const int ncol = n0 + wn * 64 + ni * 8 + (lane & 3) * 2;
            const float2 b2 = *reinterpret_cast<const float2*>(bias + ncol);
            float v00 = acc[mi][ni][0] + b2.x, v01 = acc[mi][ni][1] + b2.y;
            float v10 = acc[mi][ni][2] + b2.x, v11 = acc[mi][ni][3] + b2.y;
            if (Chi) {
                uint32_t h0, l0, h1, l1;
                split2(v00, v01, h0, l0);
                split2(v10, v11, h1, l1);
                *reinterpret_cast<uint32_t*>(Chi + (size_t)r_lo * Ndim + ncol) = h0;
                *reinterpret_cast<uint32_t*>(Clo + (size_t)r_lo * Ndim + ncol) = l0;
                *reinterpret_cast<uint32_t*>(Chi + (size_t)r_hi * Ndim + ncol) = h1;
                *reinterpret_cast<uint32_t*>(Clo + (size_t)r_hi * Ndim + ncol) = l1;
            } else {
                float2 w0; w0.x = v00; w0.y = v01;
                float2 w1; w1.x = v10; w1.y = v11;
                *reinterpret_cast<float2*>(C + (size_t)r_lo * Ndim + ncol) = w0;
                *reinterpret_cast<float2*>(C + (size_t)r_hi * Ndim + ncol) = w1;
            }
        }
    }
}

// =================== mma.sync flash attention (split bf16, causal) ===================
// CTA: 128 q-rows, 8 warps x 16 rows. KV tile = 64. Double-buffered cp.async.
// SMEM: Qh 32KB | Ql 32KB | 2 stages x (Kh,Kl,Vh,Vl = 64KB) = 192KB total.
#define ABC 64
#define ATT_SMEM (65536 + 2 * 65536)

__global__ __launch_bounds__(256, 1)
void flash_attn_mma(const bf16* __restrict__ qh, const bf16* __restrict__ ql,
                    bf16* __restrict__ outh, bf16* __restrict__ outl)
{
    extern __shared__ char smem[];
    const uint32_t sbase = smem_u32(smem);
    const uint32_t sQh = sbase, sQl = sbase + 32768;
    const int tid = threadIdx.x, wid = tid >> 5, lane = tid & 31;
    const int bh = blockIdx.y, b = bh >> 4, h = bh & 15;
    const int qt = (int)gridDim.x - 1 - (int)blockIdx.x;   // heavy tiles first
    const int q0 = qt * 128;
    const int mq = wid * 16;
    const float scale = 0.08838834764831845f;

    const size_t qoff = (size_t)b * S_ * QKV_ + (size_t)h * DH_;

    // ---- load Q (hi/lo) into SMEM ----
    {
        const int c16 = tid & 15;
#pragma unroll
        for (int it = 0; it < 8; it++) {
            int row = (tid >> 4) + it * 16;
            uint32_t so = sw256(row, c16 * 16);
            size_t go = qoff + (size_t)(q0 + row) * QKV_ + c16 * 8;
            CP_ASYNC16(sQh + so, qh + go);
            CP_ASYNC16(sQl + so, ql + go);
        }
    }

    auto load_kv = [&](int jt, int buf) {
        const uint32_t bb = sbase + 65536 + buf * 65536;
        const int k0 = jt * ABC;
        const int c16 = tid & 15;
#pragma unroll
        for (int it = 0; it < 4; it++) {
            int row = (tid >> 4) + it * 16;
            uint32_t so = sw256(row, c16 * 16);
            size_t gk = qoff + (size_t)(k0 + row) * QKV_ + DM_ + c16 * 8;
            size_t gv = gk + DM_;
            CP_ASYNC16(bb +         so, qh + gk);
            CP_ASYNC16(bb + 16384 + so, ql + gk);
            CP_ASYNC16(bb + 32768 + so, qh + gv);
            CP_ASYNC16(bb + 49152 + so, ql + gv);
        }
    };

    load_kv(0, 0);
    CP_COMMIT();

    float acc_o[16][4];
#pragma unroll
    for (int t = 0; t < 16; t++)
#pragma unroll
        for (int j = 0; j < 4; j++) acc_o[t][j] = 0.f;
    float m_st0 = -1e30f, m_st1 = -1e30f, l_st0 = 0.f, l_st1 = 0.f;

    // ldmatrix lane geometry
    const int a_row = lane & 15;
    const int a_kb  = (lane >> 4) * 16;
    const int b_row = (lane & 7) + ((lane & 16) ? 8 : 0);
    const int b_kb  = (lane & 8) ? 16 : 0;
    const int v_row = lane & 15;
    const int v_cb  = (lane & 16) ? 16 : 0;

    const int jtmax = 2 * qt + 1;
    for (int jt = 0; jt <= jtmax; jt++) {
        if (jt < jtmax) load_kv(jt + 1, (jt + 1) & 1);
        CP_COMMIT();
        CP_WAIT1();
        __syncthreads();

        const uint32_t bb = sbase + 65536 + (jt & 1) * 65536;
        const uint32_t sKh = bb, sKl = bb + 16384, sVh = bb + 32768, sVl = bb + 49152;

        // ---- S = Q K^T (3 split products) ----
        float s[8][4];
#pragma unroll
        for (int t = 0; t < 8; t++)
#pragma unroll
            for (int j = 0; j < 4; j++) s[t][j] = 0.f;

#pragma unroll
        for (int ks = 0; ks < 8; ks++) {
            uint32_t q4h[4], q4l[4];
            uint32_t soq = sw256(mq + a_row, ks * 32 + a_kb);
            LDMATRIX_X4(q4h[0], q4h[1], q4h[2], q4h[3], sQh + soq);
            LDMATRIX_X4(q4l[0], q4l[1], q4l[2], q4l[3], sQl + soq);
#pragma unroll
            for (int nb = 0; nb < 4; nb++) {
                uint32_t k4h[4], k4l[4];
                uint32_t sok = sw256(nb * 16 + b_row, ks * 32 + b_kb);
                LDMATRIX_X4(k4h[0], k4h[1], k4h[2], k4h[3], sKh + sok);
                LDMATRIX_X4(k4l[0], k4l[1], k4l[2], k4l[3], sKl + sok);
                const int t = nb * 2;
                mma16816(s[t],   q4h, k4h[0], k4h[1]);
                mma16816(s[t],   q4h, k4l[0], k4l[1]);
                mma16816(s[t],   q4l, k4h[0], k4h[1]);
                mma16816(s[t+1], q4h, k4h[2], k4h[3]);
                mma16816(s[t+1], q4h, k4l[2], k4l[3]);
                mma16816(s[t+1], q4l, k4h[2], k4h[3]);
            }
        }

        // ---- scale + causal mask ----
        const int k0 = jt * ABC;
        const bool domask = (jt >= 2 * qt);
        const int r0g = q0 + mq + (lane >> 2);
#pragma unroll
        for (int t = 0; t < 8; t++) {
#pragma unroll
            for (int j = 0; j < 4; j++) {
                float v = s[t][j] * scale;
                if (domask) {
                    int col = k0 + t * 8 + (lane & 3) * 2 + (j & 1);
                    int row = r0g + ((j & 2) ? 8 : 0);
                    if (col > row) v = -1e30f;
                }
                s[t][j] = v;
            }
        }

        // ---- online softmax (registers + quad shuffles) ----
        float mx0 = -1e30f, mx1 = -1e30f;
#pragma unroll
        for (int t = 0; t < 8; t++) {
            mx0 = fmaxf(mx0, fmaxf(s[t][0], s[t][1]));
            mx1 = fmaxf(mx1, fmaxf(s[t][2], s[t][3]));
        }
        mx0 = fmaxf(mx0, __shfl_xor_sync(0xffffffffu, mx0, 1));
        mx0 = fmaxf(mx0, __shfl_xor_sync(0xffffffffu, mx0, 2));
        mx1 = fmaxf(mx1, __shfl_xor_sync(0xffffffffu, mx1, 1));
        mx1 = fmaxf(mx1, __shfl_xor_sync(0xffffffffu, mx1, 2));
        const float mn0 = fmaxf(m_st0, mx0), mn1 = fmaxf(m_st1, mx1);
        const float al0 = __expf(m_st0 - mn0), al1 = __expf(m_st1 - mn1);
        float rs0 = 0.f, rs1 = 0.f;
#pragma unroll
        for (int t = 0; t < 8; t++) {
            s[t][0] = __expf(s[t][0] - mn0); rs0 += s[t][0];
            s[t][1] = __expf(s[t][1] - mn0); rs0 += s[t][1];
            s[t][2] = __expf(s[t][2] - mn1); rs1 += s[t][2];
            s[t][3] = __expf(s[t][3] - mn1); rs1 += s[t][3];
        }
        rs0 += __shfl_xor_sync(0xffffffffu, rs0, 1);
        rs0 += __shfl_xor_sync(0xffffffffu, rs0, 2);
        rs1 += __shfl_xor_sync(0xffffffffu, rs1, 1);
        rs1 += __shfl_xor_sync(0xffffffffu, rs1, 2);
        l_st0 = l_st0 * al0 + rs0; l_st1 = l_st1 * al1 + rs1;
        m_st0 = mn0; m_st1 = mn1;

        // rescale O
#pragma unroll
        for (int t = 0; t < 16; t++) {
            acc_o[t][0] *= al0; acc_o[t][1] *= al0;
            acc_o[t][2] *= al1; acc_o[t][3] *= al1;
        }

        // ---- O += P V (3 split products) ----
#pragma unroll
        for (int kk = 0; kk < 4; kk++) {
            uint32_t ph[4], pl[4];
            split2(s[2*kk][0],   s[2*kk][1],   ph[0], pl[0]);
            split2(s[2*kk][2],   s[2*kk][3],   ph[1], pl[1]);
            split2(s[2*kk+1][0], s[2*kk+1][1], ph[2], pl[2]);
            split2(s[2*kk+1][2], s[2*kk+1][3], ph[3], pl[3]);
#pragma unroll
            for (int db = 0; db < 8; db++) {
                uint32_t v4h[4], v4l[4];
                uint32_t sov = sw256(kk * 16 + v_row, db * 32 + v_cb);
                LDMATRIX_X4_T(v4h[0], v4h[1], v4h[2], v4h[3], sVh + sov);
                LDMATRIX_X4_T(v4l[0], v4l[1], v4l[2], v4l[3], sVl + sov);
                const int t = db * 2;
                mma16816(acc_o[t],   ph, v4h[0], v4h[1]);
                mma16816(acc_o[t],   ph, v4l[0], v4l[1]);
                mma16816(acc_o[t],   pl, v4h[0], v4h[1]);
                mma16816(acc_o[t+1], ph, v4h[2], v4h[3]);
                mma16816(acc_o[t+1], ph, v4l[2], v4l[3]);
                mma16816(acc_o[t+1], pl, v4h[2], v4h[3]);
            }
        }
        __syncthreads();
    }

    // ---- epilogue: normalize, split to hi/lo bf16, store ----
    const float inv0 = 1.f / l_st0, inv1 = 1.f / l_st1;
    const int grow0 = b * S_ + q0 + mq + (lane >> 2);
#pragma unroll
    for (int t = 0; t < 16; t++) {
        const int col = h * DH_ + t * 8 + (lane & 3) * 2;
        uint32_t h0, l0, h1, l1;
        split2(acc_o[t][0] * inv0, acc_o[t][1] * inv0, h0, l0);
        split2(acc_o[t][2] * inv1, acc_o[t][3] * inv1, h1, l1);
        *reinterpret_cast<uint32_t*>(outh + (size_t)grow0 * DM_ + col) = h0;
        *reinterpret_cast<uint32_t*>(outl + (size_t)grow0 * DM_ + col) = l0;
        *reinterpret_cast<uint32_t*>(outh + (size_t)(grow0 + 8) * DM_ + col) = h1;
        *reinterpret_cast<uint32_t*>(outl + (size_t)(grow0 + 8) * DM_ + col) = l1;
    }
}

// =================== launch ===================
extern "C" void kernel_launch(void* const* d_in, const int* in_sizes, int n_in,
                              void* d_out, int out_size)
{
    const float* x     = (const float*)d_in[0];
    const float* W_qkv = (const float*)d_in[1];
    const float* b_qkv = (const float*)d_in[2];
    const float* W_out = (const float*)d_in[3];
    const float* b_out = (const float*)d_in[4];
    float* out = (float*)d_out;

    bf16 *qkvh, *qkvl, *xhi, *xlo, *wqh, *wql, *woh, *wol, *ahi, *alo;
    cudaGetSymbolAddress((void**)&qkvh, g_qkvh);
    cudaGetSymbolAddress((void**)&qkvl, g_qkvl);
    cudaGetSymbolAddress((void**)&xhi, g_xhi);
    cudaGetSymbolAddress((void**)&xlo, g_xlo);
    cudaGetSymbolAddress((void**)&wqh, g_wqh);
    cudaGetSymbolAddress((void**)&wql, g_wql);
    cudaGetSymbolAddress((void**)&woh, g_woh);
    cudaGetSymbolAddress((void**)&wol, g_wol);
    cudaGetSymbolAddress((void**)&ahi, g_ahi);
    cudaGetSymbolAddress((void**)&alo, g_alo);

    // prep: split x, transpose+split weights
    {
        size_t n4 = (size_t)MROWS * DM_ / 4;
        split_x_kernel<<<(unsigned)((n4 + 255) / 256), 256>>>(x, xhi, xlo, n4);
        dim3 blk(32, 8);
        transpose_split_kernel<<<dim3(QKV_ / 32, DM_ / 32), blk>>>(W_qkv, wqh, wql, DM_, QKV_);
        transpose_split_kernel<<<dim3(DM_ / 32, DM_ / 32), blk>>>(W_out, woh, wol, DM_, DM_);
    }

    const int gemm_smem = 2 * STAGE_BYTES;   // 128KB
    cudaFuncSetAttribute(gemm_mma_split, cudaFuncAttributeMaxDynamicSharedMemorySize, gemm_smem);

    // 1) QKV projection -> bf16 hi/lo
    gemm_mma_split<<<dim3(QKV_ / GBN, MROWS / GBM), 256, gemm_smem>>>(
        xhi, xlo, wqh, wql, b_qkv, nullptr, qkvh, qkvl, QKV_, DM_);

    // 2) causal multi-head attention (tensor-core, split bf16)
    cudaFuncSetAttribute(flash_attn_mma, cudaFuncAttributeMaxDynamicSharedMemorySize, ATT_SMEM);
    flash_attn_mma<<<dim3(S_ / 128, B_ * H_), 256, ATT_SMEM>>>(qkvh, qkvl, ahi, alo);

    // 3) output projection -> fp32 d_out
    gemm_mma_split<<<dim3(DM_ / GBN, MROWS / GBM), 256, gemm_smem>>>(
        ahi, alo, woh, wol, b_out, out, nullptr, nullptr, DM_, DM_);
}